// round 14
// baseline (speedup 1.0000x reference)
#include <cuda_runtime.h>

// Simulate_22497038696790 — batched dual-phase RK4 RSV model.
// R14 = R12 (scalar head / packed mid / scalar tail, NSUB=3, 1 warp/SMSP,
// dt-folded rates, distributed accumulation) + exact-identity segment skip:
//   days1[0]==5.0 and days2[0]==15.0 give dt==0 segments; the reference's 64
//   zero-dt RK4 steps are bitwise identities, so we store the state directly
//   (checked against the input at runtime) and shift the mid pairing so the
//   packed section pairs lane0's real segments with lane1's real segments.
//   Saves ~6 scalar-equivalent steps; outputs bit-identical to R12.
// State substitution T = 1 - D - E:
//   T' = -beta*V*T ; E' = beta*V*T - delta*E ; V' = p*E - c*V
// Output: [2, 4, 17, B] f32, index = ((phase*4 + comp)*17 + seg)*B + b

#define NSUB 3
#define NT 17
#define BLOCK 128

typedef unsigned long long u64;

static __device__ __forceinline__ u64 pk(float lo, float hi) {
    u64 r; asm("mov.b64 %0, {%1, %2};" : "=l"(r) : "f"(lo), "f"(hi)); return r;
}
static __device__ __forceinline__ void upk(u64 v, float &lo, float &hi) {
    asm("mov.b64 {%0, %1}, %2;" : "=f"(lo), "=f"(hi) : "l"(v));
}
static __device__ __forceinline__ u64 f2fma(u64 a, u64 b, u64 c) {
    u64 d; asm("fma.rn.f32x2 %0, %1, %2, %3;" : "=l"(d) : "l"(a), "l"(b), "l"(c)); return d;
}
static __device__ __forceinline__ u64 f2mul(u64 a, u64 b) {
    u64 d; asm("mul.rn.f32x2 %0, %1, %2;" : "=l"(d) : "l"(a), "l"(b)); return d;
}
static __device__ __forceinline__ u64 f2add(u64 a, u64 b) {
    u64 d; asm("add.rn.f32x2 %0, %1, %2;" : "=l"(d) : "l"(a), "l"(b)); return d;
}

// ---------------- scalar RK4 (distributed accumulation, dt-folded) ----------
static __device__ __forceinline__ void rk4s(float &T, float &E, float &V,
                                            float bd, float ndd, float pd, float ncd)
{
    const float H = 0.5f, S = 1.0f / 6.0f, TH = 1.0f / 3.0f;
    float q1 = bd * V * T;
    float e1 = fmaf(ndd, E, q1);
    float v1 = fmaf(pd, E, ncd * V);
    float Ta = fmaf(-S, q1, T), Ea = fmaf(S, e1, E), Va = fmaf(S, v1, V);
    float Tm = fmaf(-H, q1, T), Em = fmaf(H, e1, E), Vm = fmaf(H, v1, V);
    float q2 = bd * Vm * Tm;
    float e2 = fmaf(ndd, Em, q2);
    float v2 = fmaf(pd, Em, ncd * Vm);
    Ta = fmaf(-TH, q2, Ta); Ea = fmaf(TH, e2, Ea); Va = fmaf(TH, v2, Va);
    Tm = fmaf(-H, q2, T);  Em = fmaf(H, e2, E);  Vm = fmaf(H, v2, V);
    float q3 = bd * Vm * Tm;
    float e3 = fmaf(ndd, Em, q3);
    float v3 = fmaf(pd, Em, ncd * Vm);
    Ta = fmaf(-TH, q3, Ta); Ea = fmaf(TH, e3, Ea); Va = fmaf(TH, v3, Va);
    Tm = fmaf(-1.0f, q3, T); Em = E + e3; Vm = V + v3;
    float q4 = bd * Vm * Tm;
    float e4 = fmaf(ndd, Em, q4);
    float v4 = fmaf(pd, Em, ncd * Vm);
    T = fmaf(-S, q4, Ta); E = fmaf(S, e4, Ea); V = fmaf(S, v4, Va);
}

static __device__ __forceinline__ void seg_scalar(
    float &T, float &E, float &V, float dt,
    float beta, float delta, float p, float c)
{
    float bd  = beta * dt;
    float ndd = -delta * dt;
    float pd  = p * dt;
    float ncd = -c * dt;
#pragma unroll
    for (int k = 0; k < NSUB; ++k) rk4s(T, E, V, bd, ndd, pd, ncd);
}

// ---------------- packed RK4 (same distributed form) ------------------------
struct K2 { u64 half, nhalf, sixth, nsixth, third, nthird; };

static __device__ __forceinline__ void seg_packed(
    u64 &T, u64 &E, u64 &V, float dtA, float dtB,
    u64 b2, u64 nd2, u64 p2, u64 nc2, const K2 &kc)
{
    const u64 dt2 = pk(dtA, dtB);
    const u64 bd  = f2mul(b2, dt2);
    const u64 ndd = f2mul(nd2, dt2);
    const u64 pd  = f2mul(p2, dt2);
    const u64 ncd = f2mul(nc2, dt2);

#pragma unroll
    for (int k = 0; k < NSUB; ++k) {
        u64 q1 = f2mul(f2mul(bd, V), T);
        u64 e1 = f2fma(ndd, E, q1);
        u64 v1 = f2fma(pd, E, f2mul(ncd, V));
        u64 Ta = f2fma(kc.nsixth, q1, T);
        u64 Ea = f2fma(kc.sixth, e1, E);
        u64 Va = f2fma(kc.sixth, v1, V);
        u64 Tm = f2fma(kc.nhalf, q1, T);
        u64 Em = f2fma(kc.half, e1, E);
        u64 Vm = f2fma(kc.half, v1, V);
        u64 q2 = f2mul(f2mul(bd, Vm), Tm);
        u64 e2 = f2fma(ndd, Em, q2);
        u64 v2 = f2fma(pd, Em, f2mul(ncd, Vm));
        Ta = f2fma(kc.nthird, q2, Ta);
        Ea = f2fma(kc.third, e2, Ea);
        Va = f2fma(kc.third, v2, Va);
        Tm = f2fma(kc.nhalf, q2, T);
        Em = f2fma(kc.half, e2, E);
        Vm = f2fma(kc.half, v2, V);
        u64 q3 = f2mul(f2mul(bd, Vm), Tm);
        u64 e3 = f2fma(ndd, Em, q3);
        u64 v3 = f2fma(pd, Em, f2mul(ncd, Vm));
        Ta = f2fma(kc.nthird, q3, Ta);
        Ea = f2fma(kc.third, e3, Ea);
        Va = f2fma(kc.third, v3, Va);
        Tm = f2fma(pk(-1.0f, -1.0f), q3, T);
        Em = f2add(E, e3);
        Vm = f2add(V, v3);
        u64 q4 = f2mul(f2mul(bd, Vm), Tm);
        u64 e4 = f2fma(ndd, Em, q4);
        u64 v4 = f2fma(pd, Em, f2mul(ncd, Vm));
        T = f2fma(kc.nsixth, q4, Ta);
        E = f2fma(kc.sixth, e4, Ea);
        V = f2fma(kc.sixth, v4, Va);
    }
}

__global__ __launch_bounds__(BLOCK)
void Simulate_22497038696790_kernel(
    const float* __restrict__ days1, const float* __restrict__ days2,
    const float* __restrict__ D0,   const float* __restrict__ E0,
    const float* __restrict__ V01,  const float* __restrict__ V02,
    const float* __restrict__ beta_, const float* __restrict__ delta_,
    const float* __restrict__ p_,    const float* __restrict__ c_,
    const int* __restrict__ treatment,
    float* __restrict__ out, int B)
{
    int b = blockIdx.x * BLOCK + threadIdx.x;
    if (b >= B) return;

    const float beta  = beta_[b];
    const float delta = delta_[b];
    const float p     = p_[b];
    const float c     = c_[b];
    const int   treat = treatment[0];

    float d1[NT], d2[NT];
#pragma unroll
    for (int i = 0; i < NT; i++) { d1[i] = __ldg(days1 + i); d2[i] = __ldg(days2 + i); }

    // first index where days1 == 15.0 (jnp.argmax semantics: 0 if none)
    int idx15 = 0;
#pragma unroll
    for (int i = NT - 1; i >= 0; i--) if (d1[i] == 15.0f) idx15 = i;

    const unsigned uB = (unsigned)B;
    const unsigned S1 = (unsigned)NT * uB;
    const unsigned S2 = 2u * S1, S3 = 3u * S1;
    float* const o = out + b;

    // ---- Section 1: HEAD, scalar chain, phase-1 segments 0..idx15 ----
    float E1 = E0[b];
    float T1 = 1.0f - D0[b] - E1;
    float V1 = treat ? V01[b] : 0.0f;

    float t = 5.0f;
    unsigned off = 0;
    int s = 0;
    if (d1[0] == t) {                        // exact identity segment: 64
        o[off]      = 1.0f - T1 - E1;        // zero-dt RK4 steps == identity
        o[off + S1] = E1;
        o[off + S2] = V1;
        o[off + S3] = __logf(V1);
        off += uB;
        s = 1;
    }
    for (; s <= idx15; ++s) {
        float tn = d1[s];
        seg_scalar(T1, E1, V1, (tn - t) * (1.0f / NSUB), beta, delta, p, c);
        t = tn;
        o[off]      = 1.0f - T1 - E1;        // phase 0
        o[off + S1] = E1;
        o[off + S2] = V1;
        o[off + S3] = __logf(V1);
        off += uB;
    }

    // ---- Day-15 restart ----
    float T2 = T1, E2 = E1;
    float V2 = treat ? (V1 + V02[b]) : V1;

    // ---- Phase-2 segment 0 identity skip (days2[0] == 15.0) ----
    float tB = 15.0f;
    int s2 = 0;
    unsigned off2 = 4u * S1;
    if (d2[0] == tB) {
        o[off2]      = 1.0f - T2 - E2;       // phase 1, seg 0 = bolus state
        o[off2 + S1] = E2;
        o[off2 + S2] = V2;
        o[off2 + S3] = __logf(V2);
        off2 += uB;
        s2 = 1;
    }

    // ---- Section 2: MID, packed; lane0 = phase-1 rem, lane1 = phase-2 ----
    const u64 b2  = pk(beta, beta);
    const u64 nd2 = pk(-delta, -delta);
    const u64 p2  = pk(p, p);
    const u64 nc2 = pk(-c, -c);
    K2 kc;
    kc.half   = pk(0.5f, 0.5f);
    kc.nhalf  = pk(-0.5f, -0.5f);
    kc.sixth  = pk(1.0f / 6.0f, 1.0f / 6.0f);
    kc.nsixth = pk(-1.0f / 6.0f, -1.0f / 6.0f);
    kc.third  = pk(1.0f / 3.0f, 1.0f / 3.0f);
    kc.nthird = pk(-1.0f / 3.0f, -1.0f / 3.0f);

    int n1rem = NT - 1 - idx15;              // lane0 remaining segments
    int n2rem = NT - s2;                     // lane1 remaining segments
    int pairs = n1rem < n2rem ? n1rem : n2rem;

    u64 T = pk(T1, T2), E = pk(E1, E2), V = pk(V1, V2);
    float tA = t;
    int   sA = idx15 + 1;
    for (int i = 0; i < pairs; ++i) {
        float tnA = d1[sA];
        float dtA = (tnA - tA) * (1.0f / NSUB);
        float tnB = d2[s2];
        float dtB = (tnB - tB) * (1.0f / NSUB);

        seg_packed(T, E, V, dtA, dtB, b2, nd2, p2, nc2, kc);

        float Tl, Th, El, Eh, Vl, Vh;
        upk(T, Tl, Th); upk(E, El, Eh); upk(V, Vl, Vh);
        o[off]       = 1.0f - Tl - El;       // phase 0, seg sA
        o[off + S1]  = El;
        o[off + S2]  = Vl;
        o[off + S3]  = __logf(Vl);
        o[off2]      = 1.0f - Th - Eh;       // phase 1, seg s2
        o[off2 + S1] = Eh;
        o[off2 + S2] = Vh;
        o[off2 + S3] = __logf(Vh);

        off += uB; off2 += uB;
        tA = tnA; ++sA;
        tB = tnB; ++s2;
    }

    // ---- Section 3a: leftover phase-1 segments (if lane0 was longer) ----
    {
        float Tl, Th, El, Eh, Vl, Vh;
        upk(T, Tl, Th); upk(E, El, Eh); upk(V, Vl, Vh);
        T1 = Tl; E1 = El; V1 = Vl;
        T2 = Th; E2 = Eh; V2 = Vh;
    }
    for (; sA < NT; ++sA) {
        float tnA = d1[sA];
        seg_scalar(T1, E1, V1, (tnA - tA) * (1.0f / NSUB), beta, delta, p, c);
        tA = tnA;
        o[off]      = 1.0f - T1 - E1;        // phase 0
        o[off + S1] = E1;
        o[off + S2] = V1;
        o[off + S3] = __logf(V1);
        off += uB;
    }

    // ---- Section 3b: END, scalar chain, remaining phase-2 segments ----
    for (; s2 < NT; ++s2) {
        float tnB = d2[s2];
        seg_scalar(T2, E2, V2, (tnB - tB) * (1.0f / NSUB), beta, delta, p, c);
        tB = tnB;
        o[off2]      = 1.0f - T2 - E2;       // phase 1
        o[off2 + S1] = E2;
        o[off2 + S2] = V2;
        o[off2 + S3] = __logf(V2);
        off2 += uB;
    }
}

extern "C" void kernel_launch(void* const* d_in, const int* in_sizes, int n_in,
                              void* d_out, int out_size)
{
    const float* days1 = (const float*)d_in[0];
    const float* days2 = (const float*)d_in[1];
    const float* D0    = (const float*)d_in[2];
    const float* E0    = (const float*)d_in[3];
    const float* V01   = (const float*)d_in[4];
    const float* V02   = (const float*)d_in[5];
    const float* beta  = (const float*)d_in[6];
    const float* delta = (const float*)d_in[7];
    const float* p     = (const float*)d_in[8];
    const float* c     = (const float*)d_in[9];
    const int*   treat = (const int*)d_in[10];

    int B = in_sizes[2];
    int grid = (B + BLOCK - 1) / BLOCK;
    Simulate_22497038696790_kernel<<<grid, BLOCK>>>(
        days1, days2, D0, E0, V01, V02, beta, delta, p, c, treat,
        (float*)d_out, B);
}

// round 15
// speedup vs baseline: 1.1629x; 1.1629x over previous
#include <cuda_runtime.h>

// Simulate_22497038696790 — batched dual-phase RK4 RSV model.
// R15 = R12 + statically-specialized fast path:
//   When (idx15==10 && days1[0]==5 && days2[0]==15) — the dataset's actual
//   shape — run a fully-unrolled version: compile-time trip counts (day
//   values live in registers, no LDL), both phase-lead zero-dt segments
//   skipped statically (bitwise identity), mid pairs 6 real x 6 real
//   segments, end is 10 segments. Arithmetic identical to R12 per saved
//   state => outputs bit-identical. Generic R12 path kept as fallback
//   (uniform branch, taken once).
// State substitution T = 1 - D - E:
//   T' = -beta*V*T ; E' = beta*V*T - delta*E ; V' = p*E - c*V
// NSUB=3. Output: [2,4,17,B] f32, index = ((phase*4+comp)*17+seg)*B + b

#define NSUB 3
#define NT 17
#define BLOCK 128

typedef unsigned long long u64;

static __device__ __forceinline__ u64 pk(float lo, float hi) {
    u64 r; asm("mov.b64 %0, {%1, %2};" : "=l"(r) : "f"(lo), "f"(hi)); return r;
}
static __device__ __forceinline__ void upk(u64 v, float &lo, float &hi) {
    asm("mov.b64 {%0, %1}, %2;" : "=f"(lo), "=f"(hi) : "l"(v));
}
static __device__ __forceinline__ u64 f2fma(u64 a, u64 b, u64 c) {
    u64 d; asm("fma.rn.f32x2 %0, %1, %2, %3;" : "=l"(d) : "l"(a), "l"(b), "l"(c)); return d;
}
static __device__ __forceinline__ u64 f2mul(u64 a, u64 b) {
    u64 d; asm("mul.rn.f32x2 %0, %1, %2;" : "=l"(d) : "l"(a), "l"(b)); return d;
}
static __device__ __forceinline__ u64 f2add(u64 a, u64 b) {
    u64 d; asm("add.rn.f32x2 %0, %1, %2;" : "=l"(d) : "l"(a), "l"(b)); return d;
}

// ---------------- scalar RK4 (distributed accumulation, dt-folded) ----------
static __device__ __forceinline__ void rk4s(float &T, float &E, float &V,
                                            float bd, float ndd, float pd, float ncd)
{
    const float H = 0.5f, S = 1.0f / 6.0f, TH = 1.0f / 3.0f;
    float q1 = bd * V * T;
    float e1 = fmaf(ndd, E, q1);
    float v1 = fmaf(pd, E, ncd * V);
    float Ta = fmaf(-S, q1, T), Ea = fmaf(S, e1, E), Va = fmaf(S, v1, V);
    float Tm = fmaf(-H, q1, T), Em = fmaf(H, e1, E), Vm = fmaf(H, v1, V);
    float q2 = bd * Vm * Tm;
    float e2 = fmaf(ndd, Em, q2);
    float v2 = fmaf(pd, Em, ncd * Vm);
    Ta = fmaf(-TH, q2, Ta); Ea = fmaf(TH, e2, Ea); Va = fmaf(TH, v2, Va);
    Tm = fmaf(-H, q2, T);  Em = fmaf(H, e2, E);  Vm = fmaf(H, v2, V);
    float q3 = bd * Vm * Tm;
    float e3 = fmaf(ndd, Em, q3);
    float v3 = fmaf(pd, Em, ncd * Vm);
    Ta = fmaf(-TH, q3, Ta); Ea = fmaf(TH, e3, Ea); Va = fmaf(TH, v3, Va);
    Tm = fmaf(-1.0f, q3, T); Em = E + e3; Vm = V + v3;
    float q4 = bd * Vm * Tm;
    float e4 = fmaf(ndd, Em, q4);
    float v4 = fmaf(pd, Em, ncd * Vm);
    T = fmaf(-S, q4, Ta); E = fmaf(S, e4, Ea); V = fmaf(S, v4, Va);
}

static __device__ __forceinline__ void seg_scalar(
    float &T, float &E, float &V, float dt,
    float beta, float delta, float p, float c)
{
    float bd  = beta * dt;
    float ndd = -delta * dt;
    float pd  = p * dt;
    float ncd = -c * dt;
#pragma unroll
    for (int k = 0; k < NSUB; ++k) rk4s(T, E, V, bd, ndd, pd, ncd);
}

// ---------------- packed RK4 (same distributed form) ------------------------
struct K2 { u64 half, nhalf, sixth, nsixth, third, nthird; };

static __device__ __forceinline__ void seg_packed(
    u64 &T, u64 &E, u64 &V, float dtA, float dtB,
    u64 b2, u64 nd2, u64 p2, u64 nc2, const K2 &kc)
{
    const u64 dt2 = pk(dtA, dtB);
    const u64 bd  = f2mul(b2, dt2);
    const u64 ndd = f2mul(nd2, dt2);
    const u64 pd  = f2mul(p2, dt2);
    const u64 ncd = f2mul(nc2, dt2);

#pragma unroll
    for (int k = 0; k < NSUB; ++k) {
        u64 q1 = f2mul(f2mul(bd, V), T);
        u64 e1 = f2fma(ndd, E, q1);
        u64 v1 = f2fma(pd, E, f2mul(ncd, V));
        u64 Ta = f2fma(kc.nsixth, q1, T);
        u64 Ea = f2fma(kc.sixth, e1, E);
        u64 Va = f2fma(kc.sixth, v1, V);
        u64 Tm = f2fma(kc.nhalf, q1, T);
        u64 Em = f2fma(kc.half, e1, E);
        u64 Vm = f2fma(kc.half, v1, V);
        u64 q2 = f2mul(f2mul(bd, Vm), Tm);
        u64 e2 = f2fma(ndd, Em, q2);
        u64 v2 = f2fma(pd, Em, f2mul(ncd, Vm));
        Ta = f2fma(kc.nthird, q2, Ta);
        Ea = f2fma(kc.third, e2, Ea);
        Va = f2fma(kc.third, v2, Va);
        Tm = f2fma(kc.nhalf, q2, T);
        Em = f2fma(kc.half, e2, E);
        Vm = f2fma(kc.half, v2, V);
        u64 q3 = f2mul(f2mul(bd, Vm), Tm);
        u64 e3 = f2fma(ndd, Em, q3);
        u64 v3 = f2fma(pd, Em, f2mul(ncd, Vm));
        Ta = f2fma(kc.nthird, q3, Ta);
        Ea = f2fma(kc.third, e3, Ea);
        Va = f2fma(kc.third, v3, Va);
        Tm = f2fma(pk(-1.0f, -1.0f), q3, T);
        Em = f2add(E, e3);
        Vm = f2add(V, v3);
        u64 q4 = f2mul(f2mul(bd, Vm), Tm);
        u64 e4 = f2fma(ndd, Em, q4);
        u64 v4 = f2fma(pd, Em, f2mul(ncd, Vm));
        T = f2fma(kc.nsixth, q4, Ta);
        E = f2fma(kc.sixth, e4, Ea);
        V = f2fma(kc.sixth, v4, Va);
    }
}

__global__ __launch_bounds__(BLOCK)
void Simulate_22497038696790_kernel(
    const float* __restrict__ days1, const float* __restrict__ days2,
    const float* __restrict__ D0,   const float* __restrict__ E0,
    const float* __restrict__ V01,  const float* __restrict__ V02,
    const float* __restrict__ beta_, const float* __restrict__ delta_,
    const float* __restrict__ p_,    const float* __restrict__ c_,
    const int* __restrict__ treatment,
    float* __restrict__ out, int B)
{
    int b = blockIdx.x * BLOCK + threadIdx.x;
    if (b >= B) return;

    const float beta  = beta_[b];
    const float delta = delta_[b];
    const float p     = p_[b];
    const float c     = c_[b];
    const int   treat = treatment[0];

    float d1[NT], d2[NT];
#pragma unroll
    for (int i = 0; i < NT; i++) { d1[i] = __ldg(days1 + i); d2[i] = __ldg(days2 + i); }

    // first index where days1 == 15.0 (jnp.argmax semantics: 0 if none)
    int idx15 = 0;
#pragma unroll
    for (int i = NT - 1; i >= 0; i--) if (d1[i] == 15.0f) idx15 = i;

    const unsigned uB = (unsigned)B;
    const unsigned S1 = (unsigned)NT * uB;
    const unsigned S2 = 2u * S1, S3 = 3u * S1;
    float* const o = out + b;

    float E1 = E0[b];
    float T1 = 1.0f - D0[b] - E1;
    float V1 = treat ? V01[b] : 0.0f;

    const u64 b2  = pk(beta, beta);
    const u64 nd2 = pk(-delta, -delta);
    const u64 p2  = pk(p, p);
    const u64 nc2 = pk(-c, -c);
    K2 kc;
    kc.half   = pk(0.5f, 0.5f);
    kc.nhalf  = pk(-0.5f, -0.5f);
    kc.sixth  = pk(1.0f / 6.0f, 1.0f / 6.0f);
    kc.nsixth = pk(-1.0f / 6.0f, -1.0f / 6.0f);
    kc.third  = pk(1.0f / 3.0f, 1.0f / 3.0f);
    kc.nthird = pk(-1.0f / 3.0f, -1.0f / 3.0f);

#define STORE4(base, Tv, Ev, Vv)          \
    do {                                  \
        o[(base)]      = 1.0f - (Tv) - (Ev); \
        o[(base) + S1] = (Ev);            \
        o[(base) + S2] = (Vv);            \
        o[(base) + S3] = __logf(Vv);      \
    } while (0)

    if (idx15 == 10 && d1[0] == 5.0f && d2[0] == 15.0f) {
        // ================= FAST PATH: fully static structure =================
        // phase-1 seg 0: zero-dt => exact identity
        STORE4(0u, T1, E1, V1);

        // head: phase-1 segments 1..10 (5 -> 15), scalar, fully unrolled
        float t = 5.0f;
#pragma unroll
        for (int s = 1; s <= 10; ++s) {
            float tn = d1[s];                          // static index
            seg_scalar(T1, E1, V1, (tn - t) * (1.0f / NSUB), beta, delta, p, c);
            t = tn;
            STORE4((unsigned)s * uB, T1, E1, V1);
        }

        // day-15 restart; phase-2 seg 0: zero-dt => identity (bolus state)
        float T2 = T1, E2 = E1;
        float V2 = treat ? (V1 + V02[b]) : V1;
        STORE4(4u * S1, T2, E2, V2);

        // mid: 6 packed segments; lane0 = phase-1 segs 11..16,
        //      lane1 = phase-2 segs 1..6 — all real
        u64 T = pk(T1, T2), E = pk(E1, E2), V = pk(V1, V2);
        float tA = d1[10], tB = d2[0];
#pragma unroll
        for (int i = 0; i < 6; ++i) {
            float tnA = d1[11 + i];
            float tnB = d2[1 + i];
            seg_packed(T, E, V, (tnA - tA) * (1.0f / NSUB),
                       (tnB - tB) * (1.0f / NSUB), b2, nd2, p2, nc2, kc);
            float Tl, Th, El, Eh, Vl, Vh;
            upk(T, Tl, Th); upk(E, El, Eh); upk(V, Vl, Vh);
            STORE4((unsigned)(11 + i) * uB, Tl, El, Vl);          // phase 0
            STORE4(4u * S1 + (unsigned)(1 + i) * uB, Th, Eh, Vh); // phase 1
            tA = tnA; tB = tnB;
        }

        // end: phase-2 segments 7..16, scalar, fully unrolled
        {
            float Tl, Th, El, Eh, Vl, Vh;
            upk(T, Tl, Th); upk(E, El, Eh); upk(V, Vl, Vh);
            T2 = Th; E2 = Eh; V2 = Vh;
        }
#pragma unroll
        for (int s = 7; s < NT; ++s) {
            float tn = d2[s];
            seg_scalar(T2, E2, V2, (tn - tB) * (1.0f / NSUB), beta, delta, p, c);
            tB = tn;
            STORE4(4u * S1 + (unsigned)s * uB, T2, E2, V2);
        }
    } else {
        // ================= GENERIC PATH (R12 verbatim) =======================
        float t = 5.0f;
        unsigned off = 0;
        for (int s = 0; s <= idx15; ++s) {
            float tn = d1[s];
            seg_scalar(T1, E1, V1, (tn - t) * (1.0f / NSUB), beta, delta, p, c);
            t = tn;
            STORE4(off, T1, E1, V1);
            off += uB;
        }

        float T2 = T1, E2 = E1;
        float V2 = treat ? (V1 + V02[b]) : V1;

        int n1rem = NT - 1 - idx15;
        u64 T = pk(T1, T2), E = pk(E1, E2), V = pk(V1, V2);
        float tA = t, tB = 15.0f;
        int   sA = idx15 + 1;
        int   s2 = 0;
        unsigned off2 = 4u * S1;
        for (; s2 < n1rem; ++s2) {
            float tnA = d1[sA];
            float tnB = d2[s2];
            seg_packed(T, E, V, (tnA - tA) * (1.0f / NSUB),
                       (tnB - tB) * (1.0f / NSUB), b2, nd2, p2, nc2, kc);
            float Tl, Th, El, Eh, Vl, Vh;
            upk(T, Tl, Th); upk(E, El, Eh); upk(V, Vl, Vh);
            STORE4(off, Tl, El, Vl);
            STORE4(off2, Th, Eh, Vh);
            off += uB; off2 += uB;
            tA = tnA; ++sA;
            tB = tnB;
        }

        {
            float Tl, Th, El, Eh, Vl, Vh;
            upk(T, Tl, Th); upk(E, El, Eh); upk(V, Vl, Vh);
            T2 = Th; E2 = Eh; V2 = Vh;
        }
        for (; s2 < NT; ++s2) {
            float tnB = d2[s2];
            seg_scalar(T2, E2, V2, (tnB - tB) * (1.0f / NSUB), beta, delta, p, c);
            tB = tnB;
            STORE4(off2, T2, E2, V2);
            off2 += uB;
        }
    }
#undef STORE4
}

extern "C" void kernel_launch(void* const* d_in, const int* in_sizes, int n_in,
                              void* d_out, int out_size)
{
    const float* days1 = (const float*)d_in[0];
    const float* days2 = (const float*)d_in[1];
    const float* D0    = (const float*)d_in[2];
    const float* E0    = (const float*)d_in[3];
    const float* V01   = (const float*)d_in[4];
    const float* V02   = (const float*)d_in[5];
    const float* beta  = (const float*)d_in[6];
    const float* delta = (const float*)d_in[7];
    const float* p     = (const float*)d_in[8];
    const float* c     = (const float*)d_in[9];
    const int*   treat = (const int*)d_in[10];

    int B = in_sizes[2];
    int grid = (B + BLOCK - 1) / BLOCK;
    Simulate_22497038696790_kernel<<<grid, BLOCK>>>(
        days1, days2, D0, E0, V01, V02, beta, delta, p, c, treat,
        (float*)d_out, B);
}

// round 16
// speedup vs baseline: 1.1867x; 1.0205x over previous
#include <cuda_runtime.h>

// Simulate_22497038696790 — batched dual-phase RK4 RSV model.  FINAL (= R12).
// Structure proven optimal over 15 measured rounds:
//   - 1 trajectory/thread, 128 blocks x 128 threads = 1 warp/SMSP on 128 SMs
//     (512 warps < 592 SMSPs; co-residency measured to regress — R9)
//   - NSUB=3 substeps/segment (RK4 err ~ dt^4; measured rel_err 3.25e-4 vs
//     1e-3 threshold; NSUB=2 analytically exceeds budget)
//   - scalar head (5->15) / packed-f32x2 mid (6 dual-phase segments) /
//     scalar tail: packing only where both lanes carry distinct chains
//     (FFMA2 rt_SMSP~4 => issue-neutral otherwise — R7/R8)
//   - dt-folded rates + distributed RK4 accumulation (stage constants are
//     compile-time immediates; accumulator FMAs fill latency shadows — R5)
//   - rolled loops with static bodies: full unroll blows I$ (R15), dynamic
//     day-indexing spills to local memory (R14)
//   - no dt==0 guards: zero-dt steps are exact bitwise identities (R12)
// State substitution T = 1 - D - E (affine => RK4-identical):
//   T' = -beta*V*T ; E' = beta*V*T - delta*E ; V' = p*E - c*V
// Output: [2, 4, 17, B] f32, index = ((phase*4 + comp)*17 + seg)*B + b

#define NSUB 3
#define NT 17
#define BLOCK 128

typedef unsigned long long u64;

static __device__ __forceinline__ u64 pk(float lo, float hi) {
    u64 r; asm("mov.b64 %0, {%1, %2};" : "=l"(r) : "f"(lo), "f"(hi)); return r;
}
static __device__ __forceinline__ void upk(u64 v, float &lo, float &hi) {
    asm("mov.b64 {%0, %1}, %2;" : "=f"(lo), "=f"(hi) : "l"(v));
}
static __device__ __forceinline__ u64 f2fma(u64 a, u64 b, u64 c) {
    u64 d; asm("fma.rn.f32x2 %0, %1, %2, %3;" : "=l"(d) : "l"(a), "l"(b), "l"(c)); return d;
}
static __device__ __forceinline__ u64 f2mul(u64 a, u64 b) {
    u64 d; asm("mul.rn.f32x2 %0, %1, %2;" : "=l"(d) : "l"(a), "l"(b)); return d;
}
static __device__ __forceinline__ u64 f2add(u64 a, u64 b) {
    u64 d; asm("add.rn.f32x2 %0, %1, %2;" : "=l"(d) : "l"(a), "l"(b)); return d;
}

// ---------------- scalar RK4 (distributed accumulation, dt-folded) ----------
static __device__ __forceinline__ void rk4s(float &T, float &E, float &V,
                                            float bd, float ndd, float pd, float ncd)
{
    const float H = 0.5f, S = 1.0f / 6.0f, TH = 1.0f / 3.0f;
    float q1 = bd * V * T;
    float e1 = fmaf(ndd, E, q1);
    float v1 = fmaf(pd, E, ncd * V);
    float Ta = fmaf(-S, q1, T), Ea = fmaf(S, e1, E), Va = fmaf(S, v1, V);
    float Tm = fmaf(-H, q1, T), Em = fmaf(H, e1, E), Vm = fmaf(H, v1, V);
    float q2 = bd * Vm * Tm;
    float e2 = fmaf(ndd, Em, q2);
    float v2 = fmaf(pd, Em, ncd * Vm);
    Ta = fmaf(-TH, q2, Ta); Ea = fmaf(TH, e2, Ea); Va = fmaf(TH, v2, Va);
    Tm = fmaf(-H, q2, T);  Em = fmaf(H, e2, E);  Vm = fmaf(H, v2, V);
    float q3 = bd * Vm * Tm;
    float e3 = fmaf(ndd, Em, q3);
    float v3 = fmaf(pd, Em, ncd * Vm);
    Ta = fmaf(-TH, q3, Ta); Ea = fmaf(TH, e3, Ea); Va = fmaf(TH, v3, Va);
    Tm = fmaf(-1.0f, q3, T); Em = E + e3; Vm = V + v3;
    float q4 = bd * Vm * Tm;
    float e4 = fmaf(ndd, Em, q4);
    float v4 = fmaf(pd, Em, ncd * Vm);
    T = fmaf(-S, q4, Ta); E = fmaf(S, e4, Ea); V = fmaf(S, v4, Va);
}

static __device__ __forceinline__ void seg_scalar(
    float &T, float &E, float &V, float dt,
    float beta, float delta, float p, float c)
{
    float bd  = beta * dt;
    float ndd = -delta * dt;
    float pd  = p * dt;
    float ncd = -c * dt;
#pragma unroll
    for (int k = 0; k < NSUB; ++k) rk4s(T, E, V, bd, ndd, pd, ncd);
}

// ---------------- packed RK4 (same distributed form) ------------------------
struct K2 { u64 half, nhalf, sixth, nsixth, third, nthird, none; };

static __device__ __forceinline__ void seg_packed(
    u64 &T, u64 &E, u64 &V, float dtA, float dtB,
    u64 b2, u64 nd2, u64 p2, u64 nc2, const K2 &kc)
{
    const u64 dt2 = pk(dtA, dtB);
    const u64 bd  = f2mul(b2, dt2);
    const u64 ndd = f2mul(nd2, dt2);
    const u64 pd  = f2mul(p2, dt2);
    const u64 ncd = f2mul(nc2, dt2);

#pragma unroll
    for (int k = 0; k < NSUB; ++k) {
        u64 q1 = f2mul(f2mul(bd, V), T);
        u64 e1 = f2fma(ndd, E, q1);
        u64 v1 = f2fma(pd, E, f2mul(ncd, V));
        u64 Ta = f2fma(kc.nsixth, q1, T);
        u64 Ea = f2fma(kc.sixth, e1, E);
        u64 Va = f2fma(kc.sixth, v1, V);
        u64 Tm = f2fma(kc.nhalf, q1, T);
        u64 Em = f2fma(kc.half, e1, E);
        u64 Vm = f2fma(kc.half, v1, V);
        u64 q2 = f2mul(f2mul(bd, Vm), Tm);
        u64 e2 = f2fma(ndd, Em, q2);
        u64 v2 = f2fma(pd, Em, f2mul(ncd, Vm));
        Ta = f2fma(kc.nthird, q2, Ta);
        Ea = f2fma(kc.third, e2, Ea);
        Va = f2fma(kc.third, v2, Va);
        Tm = f2fma(kc.nhalf, q2, T);
        Em = f2fma(kc.half, e2, E);
        Vm = f2fma(kc.half, v2, V);
        u64 q3 = f2mul(f2mul(bd, Vm), Tm);
        u64 e3 = f2fma(ndd, Em, q3);
        u64 v3 = f2fma(pd, Em, f2mul(ncd, Vm));
        Ta = f2fma(kc.nthird, q3, Ta);
        Ea = f2fma(kc.third, e3, Ea);
        Va = f2fma(kc.third, v3, Va);
        Tm = f2fma(kc.none, q3, T);
        Em = f2add(E, e3);
        Vm = f2add(V, v3);
        u64 q4 = f2mul(f2mul(bd, Vm), Tm);
        u64 e4 = f2fma(ndd, Em, q4);
        u64 v4 = f2fma(pd, Em, f2mul(ncd, Vm));
        T = f2fma(kc.nsixth, q4, Ta);
        E = f2fma(kc.sixth, e4, Ea);
        V = f2fma(kc.sixth, v4, Va);
    }
}

__global__ __launch_bounds__(BLOCK)
void Simulate_22497038696790_kernel(
    const float* __restrict__ days1, const float* __restrict__ days2,
    const float* __restrict__ D0,   const float* __restrict__ E0,
    const float* __restrict__ V01,  const float* __restrict__ V02,
    const float* __restrict__ beta_, const float* __restrict__ delta_,
    const float* __restrict__ p_,    const float* __restrict__ c_,
    const int* __restrict__ treatment,
    float* __restrict__ out, int B)
{
    int b = blockIdx.x * BLOCK + threadIdx.x;
    if (b >= B) return;

    const float beta  = beta_[b];
    const float delta = delta_[b];
    const float p     = p_[b];
    const float c     = c_[b];
    const int   treat = treatment[0];

    float d1[NT], d2[NT];
#pragma unroll
    for (int i = 0; i < NT; i++) { d1[i] = __ldg(days1 + i); d2[i] = __ldg(days2 + i); }

    // first index where days1 == 15.0 (jnp.argmax semantics: 0 if none)
    int idx15 = 0;
#pragma unroll
    for (int i = NT - 1; i >= 0; i--) if (d1[i] == 15.0f) idx15 = i;

    const size_t sB = (size_t)B;
    const size_t strideC = (size_t)NT * sB;

    // ---- Section 1: HEAD, scalar chain, phase-1 segments 0..idx15 ----
    float E1 = E0[b];
    float T1 = 1.0f - D0[b] - E1;
    float V1 = treat ? V01[b] : 0.0f;

    float t = 5.0f;
    for (int s = 0; s <= idx15; ++s) {
        float tn = d1[s];
        seg_scalar(T1, E1, V1, (tn - t) * (1.0f / NSUB), beta, delta, p, c);
        t = tn;
        size_t base = (size_t)s * sB + b;                      // phase 0
        out[base]               = 1.0f - T1 - E1;
        out[base + 1 * strideC] = E1;
        out[base + 2 * strideC] = V1;
        out[base + 3 * strideC] = __logf(V1);
    }

    // ---- Day-15 restart ----
    float T2 = T1, E2 = E1;
    float V2 = treat ? (V1 + V02[b]) : V1;

    // ---- Section 2: MID, packed; lane0 = phase-1 rem, lane1 = phase-2 ----
    const u64 b2  = pk(beta, beta);
    const u64 nd2 = pk(-delta, -delta);
    const u64 p2  = pk(p, p);
    const u64 nc2 = pk(-c, -c);
    K2 kc;
    kc.half   = pk(0.5f, 0.5f);
    kc.nhalf  = pk(-0.5f, -0.5f);
    kc.sixth  = pk(1.0f / 6.0f, 1.0f / 6.0f);
    kc.nsixth = pk(-1.0f / 6.0f, -1.0f / 6.0f);
    kc.third  = pk(1.0f / 3.0f, 1.0f / 3.0f);
    kc.nthird = pk(-1.0f / 3.0f, -1.0f / 3.0f);
    kc.none   = pk(-1.0f, -1.0f);

    int n1rem = NT - 1 - idx15;          // paired segment count

    u64 T = pk(T1, T2), E = pk(E1, E2), V = pk(V1, V2);
    float tA = t, tB = 15.0f;
    int   sA = idx15 + 1;
    int   s2 = 0;
    for (; s2 < n1rem; ++s2) {
        float tnA = d1[sA];
        float dtA = (tnA - tA) * (1.0f / NSUB);
        float tnB = d2[s2];
        float dtB = (tnB - tB) * (1.0f / NSUB);

        seg_packed(T, E, V, dtA, dtB, b2, nd2, p2, nc2, kc);

        float Tl, Th, El, Eh, Vl, Vh;
        upk(T, Tl, Th); upk(E, El, Eh); upk(V, Vl, Vh);
        size_t base1 = (size_t)sA * sB + b;                    // phase 0
        out[base1]               = 1.0f - Tl - El;
        out[base1 + 1 * strideC] = El;
        out[base1 + 2 * strideC] = Vl;
        out[base1 + 3 * strideC] = __logf(Vl);
        size_t base2 = ((size_t)4 * NT + s2) * sB + b;         // phase 1
        out[base2]               = 1.0f - Th - Eh;
        out[base2 + 1 * strideC] = Eh;
        out[base2 + 2 * strideC] = Vh;
        out[base2 + 3 * strideC] = __logf(Vh);

        tA = tnA; ++sA;
        tB = tnB;
    }

    // ---- Section 3: END, scalar chain, phase-2 segments n1rem..NT-1 ----
    {
        float Tl, Th, El, Eh, Vl, Vh;
        upk(T, Tl, Th); upk(E, El, Eh); upk(V, Vl, Vh);
        T2 = Th; E2 = Eh; V2 = Vh;
    }
    for (; s2 < NT; ++s2) {
        float tnB = d2[s2];
        seg_scalar(T2, E2, V2, (tnB - tB) * (1.0f / NSUB), beta, delta, p, c);
        tB = tnB;
        size_t base = ((size_t)4 * NT + s2) * sB + b;          // phase 1
        out[base]               = 1.0f - T2 - E2;
        out[base + 1 * strideC] = E2;
        out[base + 2 * strideC] = V2;
        out[base + 3 * strideC] = __logf(V2);
    }
}

extern "C" void kernel_launch(void* const* d_in, const int* in_sizes, int n_in,
                              void* d_out, int out_size)
{
    const float* days1 = (const float*)d_in[0];
    const float* days2 = (const float*)d_in[1];
    const float* D0    = (const float*)d_in[2];
    const float* E0    = (const float*)d_in[3];
    const float* V01   = (const float*)d_in[4];
    const float* V02   = (const float*)d_in[5];
    const float* beta  = (const float*)d_in[6];
    const float* delta = (const float*)d_in[7];
    const float* p     = (const float*)d_in[8];
    const float* c     = (const float*)d_in[9];
    const int*   treat = (const int*)d_in[10];

    int B = in_sizes[2];
    int grid = (B + BLOCK - 1) / BLOCK;
    Simulate_22497038696790_kernel<<<grid, BLOCK>>>(
        days1, days2, D0, E0, V01, V02, beta, delta, p, c, treat,
        (float*)d_out, B);
}

// round 17
// speedup vs baseline: 1.3528x; 1.1399x over previous
#include <cuda_runtime.h>

// Simulate_22497038696790 — batched dual-phase RK4 RSV model.
// R17: composite of bench-verified-best pieces:
//   - R12 section structure: scalar head (5->15) / packed-f32x2 mid (dual
//     distinct chains) / scalar tail; rolled loops (R14/R15: unroll or
//     dynamic indexing both regress)
//   - R13 u-substitution in scalar sections: U=(beta*dt)*V => 37 ops/step
//     (q=U*T is one mul), branchless FSEL V-recovery (dt==0-safe)
//   - R9 in-loop __ldg day reads: kills the d1[]/d2[] local-memory arrays
//     (R12 ncu showed L1=10%, LDL on the serial chain each segment)
// 1 traj/thread, 128x128 = 1 warp/SMSP (co-residency regresses — R9).
// NSUB=3 (rel_err 3.2e-4 vs 1e-3; NSUB=2 exceeds budget — R5-R7 dt^4 law).
// State: T = 1 - D - E;  T' = -bVT ; E' = bVT - dE ; V' = pE - cV.
// Output: [2, 4, 17, B] f32, index = ((phase*4 + comp)*17 + seg)*B + b

#define NSUB 3
#define NT 17
#define BLOCK 128

typedef unsigned long long u64;

static __device__ __forceinline__ u64 pk(float lo, float hi) {
    u64 r; asm("mov.b64 %0, {%1, %2};" : "=l"(r) : "f"(lo), "f"(hi)); return r;
}
static __device__ __forceinline__ void upk(u64 v, float &lo, float &hi) {
    asm("mov.b64 {%0, %1}, %2;" : "=f"(lo), "=f"(hi) : "l"(v));
}
static __device__ __forceinline__ u64 f2fma(u64 a, u64 b, u64 c) {
    u64 d; asm("fma.rn.f32x2 %0, %1, %2, %3;" : "=l"(d) : "l"(a), "l"(b), "l"(c)); return d;
}
static __device__ __forceinline__ u64 f2mul(u64 a, u64 b) {
    u64 d; asm("mul.rn.f32x2 %0, %1, %2;" : "=l"(d) : "l"(a), "l"(b)); return d;
}
static __device__ __forceinline__ u64 f2add(u64 a, u64 b) {
    u64 d; asm("add.rn.f32x2 %0, %1, %2;" : "=l"(d) : "l"(a), "l"(b)); return d;
}
static __device__ __forceinline__ float frcp(float x) {
    float r; asm("rcp.approx.f32 %0, %1;" : "=f"(r) : "f"(x)); return r;
}

// -------- scalar RK4 on (T, E, U): 37 ops, distributed accumulation --------
static __device__ __forceinline__ void rk4u(float &T, float &E, float &U,
                                            float ndd, float bpd, float ncd)
{
    const float H = 0.5f, S = 1.0f / 6.0f, TH = 1.0f / 3.0f;
    float q1 = U * T;
    float e1 = fmaf(ndd, E, q1);
    float u1 = fmaf(bpd, E, ncd * U);
    float Ta = fmaf(-S, q1, T), Ea = fmaf(S, e1, E), Ua = fmaf(S, u1, U);
    float Tm = fmaf(-H, q1, T), Em = fmaf(H, e1, E), Um = fmaf(H, u1, U);
    float q2 = Um * Tm;
    float e2 = fmaf(ndd, Em, q2);
    float u2 = fmaf(bpd, Em, ncd * Um);
    Ta = fmaf(-TH, q2, Ta); Ea = fmaf(TH, e2, Ea); Ua = fmaf(TH, u2, Ua);
    Tm = fmaf(-H, q2, T);  Em = fmaf(H, e2, E);  Um = fmaf(H, u2, U);
    float q3 = Um * Tm;
    float e3 = fmaf(ndd, Em, q3);
    float u3 = fmaf(bpd, Em, ncd * Um);
    Ta = fmaf(-TH, q3, Ta); Ea = fmaf(TH, e3, Ea); Ua = fmaf(TH, u3, Ua);
    Tm = T - q3; Em = E + e3; Um = U + u3;
    float q4 = Um * Tm;
    float e4 = fmaf(ndd, Em, q4);
    float u4 = fmaf(bpd, Em, ncd * Um);
    T = fmaf(-S, q4, Ta); E = fmaf(S, e4, Ea); U = fmaf(S, u4, Ua);
}

// One scalar segment in u-space; branchless, dt==0-safe (identity + FSEL).
static __device__ __forceinline__ void seg_u(
    float &T, float &E, float &V, float dt,
    float beta, float delta, float p, float c)
{
    float bd    = beta * dt;
    float ndd   = -delta * dt;
    float ncd   = -c * dt;
    float bpd   = bd * (p * dt);
    float invbd = frcp(bd);                 // MUFU, off the serial chain
    float U     = bd * V;
#pragma unroll
    for (int k = 0; k < NSUB; ++k) rk4u(T, E, U, ndd, bpd, ncd);
    float Vn = U * invbd;                   // NaN when dt==0; discarded below
    V = (dt != 0.0f) ? Vn : V;              // FSEL, no branch
}

// ---------------- packed RK4 (R12 form; dt==0 lane => exact identity) ------
struct K2 { u64 half, nhalf, sixth, nsixth, third, nthird, none; };

static __device__ __forceinline__ void seg_packed(
    u64 &T, u64 &E, u64 &V, float dtA, float dtB,
    u64 b2, u64 nd2, u64 p2, u64 nc2, const K2 &kc)
{
    const u64 dt2 = pk(dtA, dtB);
    const u64 bd  = f2mul(b2, dt2);
    const u64 ndd = f2mul(nd2, dt2);
    const u64 pd  = f2mul(p2, dt2);
    const u64 ncd = f2mul(nc2, dt2);

#pragma unroll
    for (int k = 0; k < NSUB; ++k) {
        u64 q1 = f2mul(f2mul(bd, V), T);
        u64 e1 = f2fma(ndd, E, q1);
        u64 v1 = f2fma(pd, E, f2mul(ncd, V));
        u64 Ta = f2fma(kc.nsixth, q1, T);
        u64 Ea = f2fma(kc.sixth, e1, E);
        u64 Va = f2fma(kc.sixth, v1, V);
        u64 Tm = f2fma(kc.nhalf, q1, T);
        u64 Em = f2fma(kc.half, e1, E);
        u64 Vm = f2fma(kc.half, v1, V);
        u64 q2 = f2mul(f2mul(bd, Vm), Tm);
        u64 e2 = f2fma(ndd, Em, q2);
        u64 v2 = f2fma(pd, Em, f2mul(ncd, Vm));
        Ta = f2fma(kc.nthird, q2, Ta);
        Ea = f2fma(kc.third, e2, Ea);
        Va = f2fma(kc.third, v2, Va);
        Tm = f2fma(kc.nhalf, q2, T);
        Em = f2fma(kc.half, e2, E);
        Vm = f2fma(kc.half, v2, V);
        u64 q3 = f2mul(f2mul(bd, Vm), Tm);
        u64 e3 = f2fma(ndd, Em, q3);
        u64 v3 = f2fma(pd, Em, f2mul(ncd, Vm));
        Ta = f2fma(kc.nthird, q3, Ta);
        Ea = f2fma(kc.third, e3, Ea);
        Va = f2fma(kc.third, v3, Va);
        Tm = f2fma(kc.none, q3, T);
        Em = f2add(E, e3);
        Vm = f2add(V, v3);
        u64 q4 = f2mul(f2mul(bd, Vm), Tm);
        u64 e4 = f2fma(ndd, Em, q4);
        u64 v4 = f2fma(pd, Em, f2mul(ncd, Vm));
        T = f2fma(kc.nsixth, q4, Ta);
        E = f2fma(kc.sixth, e4, Ea);
        V = f2fma(kc.sixth, v4, Va);
    }
}

__global__ __launch_bounds__(BLOCK)
void Simulate_22497038696790_kernel(
    const float* __restrict__ days1, const float* __restrict__ days2,
    const float* __restrict__ D0,   const float* __restrict__ E0,
    const float* __restrict__ V01,  const float* __restrict__ V02,
    const float* __restrict__ beta_, const float* __restrict__ delta_,
    const float* __restrict__ p_,    const float* __restrict__ c_,
    const int* __restrict__ treatment,
    float* __restrict__ out, int B)
{
    int b = blockIdx.x * BLOCK + threadIdx.x;
    if (b >= B) return;

    const float beta  = beta_[b];
    const float delta = delta_[b];
    const float p     = p_[b];
    const float c     = c_[b];
    const int   treat = treatment[0];

    // first index where days1 == 15.0 (jnp.argmax semantics: 0 if none)
    int idx15 = 0;
#pragma unroll
    for (int i = NT - 1; i >= 0; i--) if (__ldg(days1 + i) == 15.0f) idx15 = i;

    const unsigned uB = (unsigned)B;
    const unsigned S1 = (unsigned)NT * uB;
    const unsigned S2 = 2u * S1, S3 = 3u * S1;
    float* const o = out + b;

    // ---- Section 1: HEAD, scalar u-form, phase-1 segments 0..idx15 ----
    float E1 = E0[b];
    float T1 = 1.0f - D0[b] - E1;
    float V1 = treat ? V01[b] : 0.0f;

    float t = 5.0f;
    unsigned off = 0;
    for (int s = 0; s <= idx15; ++s) {
        float tn = __ldg(days1 + s);                 // no local array (R9)
        seg_u(T1, E1, V1, (tn - t) * (1.0f / NSUB), beta, delta, p, c);
        t = tn;
        o[off]      = 1.0f - T1 - E1;                // phase 0
        o[off + S1] = E1;
        o[off + S2] = V1;
        o[off + S3] = __logf(V1);
        off += uB;
    }

    // ---- Day-15 restart ----
    float T2 = T1, E2 = E1;
    float V2 = treat ? (V1 + V02[b]) : V1;

    // ---- Section 2: MID, packed; lane0 = phase-1 rem, lane1 = phase-2 ----
    const u64 b2  = pk(beta, beta);
    const u64 nd2 = pk(-delta, -delta);
    const u64 p2  = pk(p, p);
    const u64 nc2 = pk(-c, -c);
    K2 kc;
    kc.half   = pk(0.5f, 0.5f);
    kc.nhalf  = pk(-0.5f, -0.5f);
    kc.sixth  = pk(1.0f / 6.0f, 1.0f / 6.0f);
    kc.nsixth = pk(-1.0f / 6.0f, -1.0f / 6.0f);
    kc.third  = pk(1.0f / 3.0f, 1.0f / 3.0f);
    kc.nthird = pk(-1.0f / 3.0f, -1.0f / 3.0f);
    kc.none   = pk(-1.0f, -1.0f);

    int n1rem = NT - 1 - idx15;                      // paired segment count

    u64 T = pk(T1, T2), E = pk(E1, E2), V = pk(V1, V2);
    float tA = t, tB = 15.0f;
    int   sA = idx15 + 1;
    int   s2 = 0;
    unsigned off2 = 4u * S1;
    for (; s2 < n1rem; ++s2) {
        float tnA = __ldg(days1 + sA);
        float tnB = __ldg(days2 + s2);
        float dtA = (tnA - tA) * (1.0f / NSUB);
        float dtB = (tnB - tB) * (1.0f / NSUB);

        seg_packed(T, E, V, dtA, dtB, b2, nd2, p2, nc2, kc);

        float Tl, Th, El, Eh, Vl, Vh;
        upk(T, Tl, Th); upk(E, El, Eh); upk(V, Vl, Vh);
        o[off]       = 1.0f - Tl - El;               // phase 0, seg sA
        o[off + S1]  = El;
        o[off + S2]  = Vl;
        o[off + S3]  = __logf(Vl);
        o[off2]      = 1.0f - Th - Eh;               // phase 1, seg s2
        o[off2 + S1] = Eh;
        o[off2 + S2] = Vh;
        o[off2 + S3] = __logf(Vh);

        off += uB; off2 += uB;
        tA = tnA; ++sA;
        tB = tnB;
    }

    // ---- Section 3: END, scalar u-form, phase-2 segments n1rem..NT-1 ----
    {
        float Tl, Th, El, Eh, Vl, Vh;
        upk(T, Tl, Th); upk(E, El, Eh); upk(V, Vl, Vh);
        T2 = Th; E2 = Eh; V2 = Vh;
    }
    for (; s2 < NT; ++s2) {
        float tnB = __ldg(days2 + s2);
        seg_u(T2, E2, V2, (tnB - tB) * (1.0f / NSUB), beta, delta, p, c);
        tB = tnB;
        o[off2]      = 1.0f - T2 - E2;               // phase 1
        o[off2 + S1] = E2;
        o[off2 + S2] = V2;
        o[off2 + S3] = __logf(V2);
        off2 += uB;
    }
}

extern "C" void kernel_launch(void* const* d_in, const int* in_sizes, int n_in,
                              void* d_out, int out_size)
{
    const float* days1 = (const float*)d_in[0];
    const float* days2 = (const float*)d_in[1];
    const float* D0    = (const float*)d_in[2];
    const float* E0    = (const float*)d_in[3];
    const float* V01   = (const float*)d_in[4];
    const float* V02   = (const float*)d_in[5];
    const float* beta  = (const float*)d_in[6];
    const float* delta = (const float*)d_in[7];
    const float* p     = (const float*)d_in[8];
    const float* c     = (const float*)d_in[9];
    const int*   treat = (const int*)d_in[10];

    int B = in_sizes[2];
    int grid = (B + BLOCK - 1) / BLOCK;
    Simulate_22497038696790_kernel<<<grid, BLOCK>>>(
        days1, days2, D0, E0, V01, V02, beta, delta, p, c, treat,
        (float*)d_out, B);
}